// round 1
// baseline (speedup 1.0000x reference)
#include <cuda_runtime.h>

#define NTOK 1024
#define CDIM 768
#define NH   12
#define HD   64
#define NB   8
#define BHN  (NB*NH)               /* 96  */
#define KV_ELEMS (BHN*NTOK*HD)     /* 6291456 */
#define OUT_ELEMS (NB*NTOK*CDIM)   /* 6291456 */

__device__ float g_Q[KV_ELEMS];     // unscaled q, layout (b*12+h, n, d)
__device__ float g_REL[KV_ELEMS];   // per (bh, n): [0,32)=rel_h over kh, [32,64)=rel_w over kw
__device__ float g_AO[OUT_ELEMS];   // attention output, (B, N, C) layout, pre-proj

// ---------------------------------------------------------------------------
// Kernel 1: QKV GEMM.  P = X(8192x768) @ W(2304x768)^T + b, scattered:
//   t=0 -> g_Q, t=1 -> pre_kv K half (in d_out), t=2 -> pre_kv V half.
// ---------------------------------------------------------------------------
__global__ void __launch_bounds__(256) qkv_gemm_kernel(
        const float* __restrict__ X, const float* __restrict__ W,
        const float* __restrict__ bvec, float* __restrict__ kvout)
{
    __shared__ float As[16][132];
    __shared__ float Bs[16][132];
    const int bm = blockIdx.y * 128;
    const int bn = blockIdx.x * 128;
    const int tid = threadIdx.x;
    const int tx = tid & 15, ty = tid >> 4;

    float acc[8][8];
#pragma unroll
    for (int i = 0; i < 8; i++)
#pragma unroll
        for (int j = 0; j < 8; j++) acc[i][j] = 0.f;

    for (int k0 = 0; k0 < CDIM; k0 += 16) {
#pragma unroll
        for (int u = 0; u < 2; u++) {
            int idx = tid + u * 256;
            int r = idx >> 2;
            int c4 = (idx & 3) << 2;
            float4 av = *(const float4*)(X + (size_t)(bm + r) * CDIM + k0 + c4);
            As[c4 + 0][r] = av.x; As[c4 + 1][r] = av.y;
            As[c4 + 2][r] = av.z; As[c4 + 3][r] = av.w;
            float4 wv = *(const float4*)(W + (size_t)(bn + r) * CDIM + k0 + c4);
            Bs[c4 + 0][r] = wv.x; Bs[c4 + 1][r] = wv.y;
            Bs[c4 + 2][r] = wv.z; Bs[c4 + 3][r] = wv.w;
        }
        __syncthreads();
#pragma unroll
        for (int k = 0; k < 16; k++) {
            float4 a0 = *(const float4*)&As[k][ty * 8];
            float4 a1 = *(const float4*)&As[k][ty * 8 + 4];
            float4 b0 = *(const float4*)&Bs[k][tx * 8];
            float4 b1 = *(const float4*)&Bs[k][tx * 8 + 4];
            float a[8] = {a0.x, a0.y, a0.z, a0.w, a1.x, a1.y, a1.z, a1.w};
            float b[8] = {b0.x, b0.y, b0.z, b0.w, b1.x, b1.y, b1.z, b1.w};
#pragma unroll
            for (int i = 0; i < 8; i++)
#pragma unroll
                for (int j = 0; j < 8; j++)
                    acc[i][j] += a[i] * b[j];
        }
        __syncthreads();
    }

    const int t = bn / CDIM;   // uniform per block (768 % 128 == 0)
#pragma unroll
    for (int i = 0; i < 8; i++) {
        int row = bm + ty * 8 + i;
        int b = row >> 10, n = row & (NTOK - 1);
#pragma unroll
        for (int j = 0; j < 8; j++) {
            int col = bn + tx * 8 + j;
            float v = acc[i][j] + __ldg(&bvec[col]);
            int rem = col - t * CDIM;
            int h = rem >> 6, d = rem & 63;
            size_t idx = ((size_t)(b * NH + h) << 16) | ((size_t)n << 6) | (size_t)d;
            if (t == 0)      g_Q[idx] = v;
            else if (t == 1) kvout[idx] = v;
            else             kvout[KV_ELEMS + idx] = v;
        }
    }
}

// ---------------------------------------------------------------------------
// Kernel 2: rel-pos projections.
//   g_REL[bh,q,kh]      = sum_d Q[bh,q,d] * rel_pos_h[qh-kh+31, d]   (kh<32)
//   g_REL[bh,q,32+kw]   = sum_d Q[bh,q,d] * rel_pos_w[qw-kw+31, d]
// ---------------------------------------------------------------------------
__global__ void __launch_bounds__(256) rel_kernel(
        const float* __restrict__ rph, const float* __restrict__ rpw)
{
    extern __shared__ float sm[];
    float (*Qs)[68] = (float (*)[68])sm;
    float (*Th)[68] = (float (*)[68])(sm + 64 * 68);
    float (*Tw)[68] = (float (*)[68])(sm + (64 + 63) * 68);

    const int bh = blockIdx.y;
    const int q0 = blockIdx.x * 64;
    const int tid = threadIdx.x;

    for (int i = tid; i < 64 * 16; i += 256) {
        int r = i >> 4, c = (i & 15) << 2;
        float4 v = *(const float4*)(g_Q + ((size_t)(bh * NTOK + q0 + r) << 6) + c);
        Qs[r][c] = v.x; Qs[r][c + 1] = v.y; Qs[r][c + 2] = v.z; Qs[r][c + 3] = v.w;
    }
    for (int i = tid; i < 63 * 16; i += 256) {
        int r = i >> 4, c = (i & 15) << 2;
        float4 vh = *(const float4*)(rph + r * 64 + c);
        Th[r][c] = vh.x; Th[r][c + 1] = vh.y; Th[r][c + 2] = vh.z; Th[r][c + 3] = vh.w;
        float4 vw = *(const float4*)(rpw + r * 64 + c);
        Tw[r][c] = vw.x; Tw[r][c + 1] = vw.y; Tw[r][c + 2] = vw.z; Tw[r][c + 3] = vw.w;
    }
    __syncthreads();

    const int ql = tid >> 2, j4 = tid & 3;
    const int q = q0 + ql, qh = q >> 5, qw = q & 31;
    float* outp = g_REL + ((size_t)(bh * NTOK + q) << 6);
#pragma unroll
    for (int jj = 0; jj < 16; jj++) {
        int j = j4 * 16 + jj;
        const float* T = (j < 32) ? &Th[qh - j + 31][0]
                                  : &Tw[qw - (j - 32) + 31][0];
        float s = 0.f;
#pragma unroll
        for (int d0 = 0; d0 < 64; d0 += 4) {
            float4 qv = *(const float4*)&Qs[ql][d0];
            float4 tv = *(const float4*)(T + d0);
            s += qv.x * tv.x + qv.y * tv.y + qv.z * tv.z + qv.w * tv.w;
        }
        outp[j] = s;
    }
}

// ---------------------------------------------------------------------------
// Kernel 3: fused flash attention with decomposed bias.
// Block = (bh, 64-query tile). 256 threads: thread owns q rows {qg, qg+32}
// and 8 key columns {jj*8+tx}. Online softmax; O accumulated in regs.
// ---------------------------------------------------------------------------
#define SM_TILE (64 * 68)

__global__ void __launch_bounds__(256) attn_kernel(const float* __restrict__ KV)
{
    extern __shared__ float sm[];
    float (*Qs)[68] = (float (*)[68])sm;
    float (*Ks)[68] = (float (*)[68])(sm + SM_TILE);
    float (*Vs)[68] = (float (*)[68])(sm + 2 * SM_TILE);
    float (*Ps)[68] = (float (*)[68])(sm + 3 * SM_TILE);
    float (*Rs)[68] = (float (*)[68])(sm + 4 * SM_TILE);

    const int bh = blockIdx.y;
    const int q0 = blockIdx.x * 64;
    const int tid = threadIdx.x;
    const int qg = tid >> 3;      // 0..31
    const int tx = tid & 7;       // 0..7

    for (int i = tid; i < 64 * 16; i += 256) {
        int r = i >> 4, c = (i & 15) << 2;
        size_t base = ((size_t)(bh * NTOK + q0 + r) << 6) + c;
        float4 qv = *(const float4*)(g_Q + base);
        Qs[r][c] = qv.x; Qs[r][c + 1] = qv.y; Qs[r][c + 2] = qv.z; Qs[r][c + 3] = qv.w;
        float4 rv = *(const float4*)(g_REL + base);
        Rs[r][c] = rv.x; Rs[r][c + 1] = rv.y; Rs[r][c + 2] = rv.z; Rs[r][c + 3] = rv.w;
    }

    float acc[2][8];
#pragma unroll
    for (int r = 0; r < 2; r++)
#pragma unroll
        for (int j = 0; j < 8; j++) acc[r][j] = 0.f;
    float m_i[2] = {-1e30f, -1e30f};
    float l_i[2] = {0.f, 0.f};

    const float scale = 0.125f;   // 64^-0.5
    const float* Kbase = KV + ((size_t)bh * NTOK << 6);
    const float* Vbase = KV + (size_t)KV_ELEMS + ((size_t)bh * NTOK << 6);

    for (int t = 0; t < 16; t++) {
        const int k0 = t * 64;
        __syncthreads();
        for (int i = tid; i < 64 * 16; i += 256) {
            int r = i >> 4, c = (i & 15) << 2;
            float4 kv4 = *(const float4*)(Kbase + ((size_t)(k0 + r) << 6) + c);
            Ks[r][c] = kv4.x; Ks[r][c + 1] = kv4.y; Ks[r][c + 2] = kv4.z; Ks[r][c + 3] = kv4.w;
            float4 vv4 = *(const float4*)(Vbase + ((size_t)(k0 + r) << 6) + c);
            Vs[r][c] = vv4.x; Vs[r][c + 1] = vv4.y; Vs[r][c + 2] = vv4.z; Vs[r][c + 3] = vv4.w;
        }
        __syncthreads();

        float s[2][8];
#pragma unroll
        for (int r = 0; r < 2; r++)
#pragma unroll
            for (int j = 0; j < 8; j++) s[r][j] = 0.f;

#pragma unroll
        for (int d0 = 0; d0 < 64; d0 += 4) {
            float4 q0v = *(const float4*)&Qs[qg][d0];
            float4 q1v = *(const float4*)&Qs[qg + 32][d0];
#pragma unroll
            for (int jj = 0; jj < 8; jj++) {
                float4 kv4 = *(const float4*)&Ks[jj * 8 + tx][d0];
                s[0][jj] += q0v.x * kv4.x + q0v.y * kv4.y + q0v.z * kv4.z + q0v.w * kv4.w;
                s[1][jj] += q1v.x * kv4.x + q1v.y * kv4.y + q1v.z * kv4.z + q1v.w * kv4.w;
            }
        }

        const int khb = t * 2;   // kh base for this 64-wide k tile
#pragma unroll
        for (int r = 0; r < 2; r++) {
            const int qrow = qg + r * 32;
            float mt = -1e30f;
#pragma unroll
            for (int jj = 0; jj < 8; jj++) {
                int j = jj * 8 + tx;
                float v = s[r][jj] * scale
                        + Rs[qrow][khb + (j >> 5)]
                        + Rs[qrow][32 + (j & 31)];
                s[r][jj] = v;
                mt = fmaxf(mt, v);
            }
            mt = fmaxf(mt, __shfl_xor_sync(0xffffffffu, mt, 1));
            mt = fmaxf(mt, __shfl_xor_sync(0xffffffffu, mt, 2));
            mt = fmaxf(mt, __shfl_xor_sync(0xffffffffu, mt, 4));
            float m_new = fmaxf(m_i[r], mt);
            float alpha = __expf(m_i[r] - m_new);
            float psum = 0.f;
#pragma unroll
            for (int jj = 0; jj < 8; jj++) {
                float p = __expf(s[r][jj] - m_new);
                psum += p;
                Ps[qrow][jj * 8 + tx] = p;
            }
            psum += __shfl_xor_sync(0xffffffffu, psum, 1);
            psum += __shfl_xor_sync(0xffffffffu, psum, 2);
            psum += __shfl_xor_sync(0xffffffffu, psum, 4);
            l_i[r] = l_i[r] * alpha + psum;
            m_i[r] = m_new;
#pragma unroll
            for (int j = 0; j < 8; j++) acc[r][j] *= alpha;
        }
        __syncwarp();

#pragma unroll 4
        for (int k = 0; k < 64; k++) {
            float p0 = Ps[qg][k];
            float p1 = Ps[qg + 32][k];
            float4 va = *(const float4*)&Vs[k][tx * 8];
            float4 vb = *(const float4*)&Vs[k][tx * 8 + 4];
            acc[0][0] += p0 * va.x; acc[0][1] += p0 * va.y;
            acc[0][2] += p0 * va.z; acc[0][3] += p0 * va.w;
            acc[0][4] += p0 * vb.x; acc[0][5] += p0 * vb.y;
            acc[0][6] += p0 * vb.z; acc[0][7] += p0 * vb.w;
            acc[1][0] += p1 * va.x; acc[1][1] += p1 * va.y;
            acc[1][2] += p1 * va.z; acc[1][3] += p1 * va.w;
            acc[1][4] += p1 * vb.x; acc[1][5] += p1 * vb.y;
            acc[1][6] += p1 * vb.z; acc[1][7] += p1 * vb.w;
        }
    }

    const int b = bh / NH, h = bh - b * NH;
#pragma unroll
    for (int r = 0; r < 2; r++) {
        float inv = 1.f / l_i[r];
        int qrow = q0 + qg + r * 32;
        float* op = g_AO + (size_t)(b * NTOK + qrow) * CDIM + h * HD + tx * 8;
        float4 o0 = make_float4(acc[r][0] * inv, acc[r][1] * inv,
                                acc[r][2] * inv, acc[r][3] * inv);
        float4 o1 = make_float4(acc[r][4] * inv, acc[r][5] * inv,
                                acc[r][6] * inv, acc[r][7] * inv);
        *(float4*)op = o0;
        *(float4*)(op + 4) = o1;
    }
}

// ---------------------------------------------------------------------------
// Kernel 4: output projection.  out = g_AO(8192x768) @ proj_w(768x768)^T + b
// ---------------------------------------------------------------------------
__global__ void __launch_bounds__(256) proj_gemm_kernel(
        const float* __restrict__ W, const float* __restrict__ bvec,
        float* __restrict__ out)
{
    __shared__ float As[16][132];
    __shared__ float Bs[16][132];
    const int bm = blockIdx.y * 128;
    const int bn = blockIdx.x * 128;
    const int tid = threadIdx.x;
    const int tx = tid & 15, ty = tid >> 4;

    float acc[8][8];
#pragma unroll
    for (int i = 0; i < 8; i++)
#pragma unroll
        for (int j = 0; j < 8; j++) acc[i][j] = 0.f;

    for (int k0 = 0; k0 < CDIM; k0 += 16) {
#pragma unroll
        for (int u = 0; u < 2; u++) {
            int idx = tid + u * 256;
            int r = idx >> 2;
            int c4 = (idx & 3) << 2;
            float4 av = *(const float4*)(g_AO + (size_t)(bm + r) * CDIM + k0 + c4);
            As[c4 + 0][r] = av.x; As[c4 + 1][r] = av.y;
            As[c4 + 2][r] = av.z; As[c4 + 3][r] = av.w;
            float4 wv = *(const float4*)(W + (size_t)(bn + r) * CDIM + k0 + c4);
            Bs[c4 + 0][r] = wv.x; Bs[c4 + 1][r] = wv.y;
            Bs[c4 + 2][r] = wv.z; Bs[c4 + 3][r] = wv.w;
        }
        __syncthreads();
#pragma unroll
        for (int k = 0; k < 16; k++) {
            float4 a0 = *(const float4*)&As[k][ty * 8];
            float4 a1 = *(const float4*)&As[k][ty * 8 + 4];
            float4 b0 = *(const float4*)&Bs[k][tx * 8];
            float4 b1 = *(const float4*)&Bs[k][tx * 8 + 4];
            float a[8] = {a0.x, a0.y, a0.z, a0.w, a1.x, a1.y, a1.z, a1.w};
            float b[8] = {b0.x, b0.y, b0.z, b0.w, b1.x, b1.y, b1.z, b1.w};
#pragma unroll
            for (int i = 0; i < 8; i++)
#pragma unroll
                for (int j = 0; j < 8; j++)
                    acc[i][j] += a[i] * b[j];
        }
        __syncthreads();
    }

#pragma unroll
    for (int i = 0; i < 8; i++) {
        int row = bm + ty * 8 + i;
#pragma unroll
        for (int j = 0; j < 8; j++) {
            int col = bn + tx * 8 + j;
            out[(size_t)row * CDIM + col] = acc[i][j] + __ldg(&bvec[col]);
        }
    }
}

// ---------------------------------------------------------------------------
extern "C" void kernel_launch(void* const* d_in, const int* in_sizes, int n_in,
                              void* d_out, int out_size)
{
    (void)in_sizes; (void)n_in; (void)out_size;
    const float* x      = (const float*)d_in[0];
    const float* qkv_w  = (const float*)d_in[1];
    const float* qkv_b  = (const float*)d_in[2];
    const float* proj_w = (const float*)d_in[3];
    const float* proj_b = (const float*)d_in[4];
    const float* rph    = (const float*)d_in[5];
    const float* rpw    = (const float*)d_in[6];
    float* out = (float*)d_out;
    float* kv  = out + OUT_ELEMS;   // pre_kv region: K half then V half

    cudaFuncSetAttribute(rel_kernel,  cudaFuncAttributeMaxDynamicSharedMemorySize,
                         (64 + 63 + 63) * 68 * 4);
    cudaFuncSetAttribute(attn_kernel, cudaFuncAttributeMaxDynamicSharedMemorySize,
                         5 * SM_TILE * 4);

    qkv_gemm_kernel<<<dim3(18, 64), 256>>>(x, qkv_w, qkv_b, kv);
    rel_kernel<<<dim3(16, 96), 256, (64 + 63 + 63) * 68 * 4>>>(rph, rpw);
    attn_kernel<<<dim3(16, 96), 256, 5 * SM_TILE * 4>>>(kv);
    proj_gemm_kernel<<<dim3(6, 64), 256>>>(proj_w, proj_b, out);
}

// round 3
// speedup vs baseline: 1.3132x; 1.3132x over previous
#include <cuda_runtime.h>
#include <cuda_bf16.h>
#include <cstdint>

#define NTOK 1024
#define CDIM 768
#define NH   12
#define HD   64
#define NB   8
#define BHN  (NB*NH)               /* 96  */
#define KV_ELEMS (BHN*NTOK*HD)     /* 6291456 */
#define OUT_ELEMS (NB*NTOK*CDIM)   /* 6291456 */

__device__ float g_Q[KV_ELEMS];     // unscaled q, layout (b*12+h, n, d)
__device__ float g_REL[KV_ELEMS];   // per (bh, n): [0,32)=rel_h, [32,64)=rel_w
__device__ float g_AO[OUT_ELEMS];   // attention output (B, N, C), pre-proj

// bf16 hi/lo split scratch
__device__ __nv_bfloat16 g_Xhi[OUT_ELEMS],  g_Xlo[OUT_ELEMS];
__device__ __nv_bfloat16 g_Wqhi[3*CDIM*CDIM], g_Wqlo[3*CDIM*CDIM];
__device__ __nv_bfloat16 g_Wphi[CDIM*CDIM], g_Wplo[CDIM*CDIM];
__device__ __nv_bfloat16 g_AOhi[OUT_ELEMS], g_AOlo[OUT_ELEMS];

// ---------------------------------------------------------------------------
__device__ __forceinline__ uint32_t smem_u32(const void* p) {
    uint32_t a;
    asm("{ .reg .u64 t; cvta.to.shared.u64 t, %1; cvt.u32.u64 %0, t; }" : "=r"(a) : "l"(p));
    return a;
}
__device__ __forceinline__ void ldm_x4(uint32_t* r, uint32_t addr) {
    asm volatile("ldmatrix.sync.aligned.m8n8.x4.shared.b16 {%0,%1,%2,%3}, [%4];"
                 : "=r"(r[0]), "=r"(r[1]), "=r"(r[2]), "=r"(r[3]) : "r"(addr));
}
__device__ __forceinline__ void mma16816(float* d, const uint32_t* a, const uint32_t* b) {
    asm volatile(
        "mma.sync.aligned.m16n8k16.row.col.f32.bf16.bf16.f32 "
        "{%0,%1,%2,%3}, {%4,%5,%6,%7}, {%8,%9}, {%0,%1,%2,%3};"
        : "+f"(d[0]), "+f"(d[1]), "+f"(d[2]), "+f"(d[3])
        : "r"(a[0]), "r"(a[1]), "r"(a[2]), "r"(a[3]), "r"(b[0]), "r"(b[1]));
}
__device__ __forceinline__ void sts128(uint32_t addr, uint4 v) {
    asm volatile("st.shared.v4.b32 [%0], {%1, %2, %3, %4};"
                 :: "r"(addr), "r"(v.x), "r"(v.y), "r"(v.z), "r"(v.w) : "memory");
}
// row r (32B rows of 16 bf16), 16B chunk c: xor-swizzled offset, conflict-free
__device__ __forceinline__ uint32_t tswz(int r, int c) {
    return (uint32_t)(r * 32 + 16 * (c ^ ((r >> 2) & 1)));
}

// ---------------------------------------------------------------------------
// Conversion: fp32 -> (bf16 hi, bf16 lo residual)
// ---------------------------------------------------------------------------
__global__ void __launch_bounds__(256) cvt_hilo(
        const float* __restrict__ src, __nv_bfloat16* __restrict__ hi,
        __nv_bfloat16* __restrict__ lo, int n)
{
    int i = (blockIdx.x * 256 + threadIdx.x) * 4;
    if (i >= n) return;
    float4 v = *(const float4*)(src + i);
    __nv_bfloat16 h0 = __float2bfloat16(v.x), h1 = __float2bfloat16(v.y);
    __nv_bfloat16 h2 = __float2bfloat16(v.z), h3 = __float2bfloat16(v.w);
    __nv_bfloat16 l0 = __float2bfloat16(v.x - __bfloat162float(h0));
    __nv_bfloat16 l1 = __float2bfloat16(v.y - __bfloat162float(h1));
    __nv_bfloat16 l2 = __float2bfloat16(v.z - __bfloat162float(h2));
    __nv_bfloat16 l3 = __float2bfloat16(v.w - __bfloat162float(h3));
    __nv_bfloat162* hp = (__nv_bfloat162*)(hi + i);
    hp[0] = __nv_bfloat162(h0, h1); hp[1] = __nv_bfloat162(h2, h3);
    __nv_bfloat162* lp = (__nv_bfloat162*)(lo + i);
    lp[0] = __nv_bfloat162(l0, l1); lp[1] = __nv_bfloat162(l2, l3);
}

// ---------------------------------------------------------------------------
// HMMA bf16x3 GEMM: D(128x128 tile) = A(M,768) @ B(N,768)^T + bias
//   D = Ahi*Bhi + Ahi*Blo + Alo*Bhi  (fp32 accum)
// mode 0: out0[row*768+col] (proj);  mode 1: qkv scatter.
// ---------------------------------------------------------------------------
#define STG 16384   /* per-stage: Ahi 4K | Alo 4K | Bhi 4K | Blo 4K */

__global__ void __launch_bounds__(256, 2) gemm_mma(
        const __nv_bfloat16* __restrict__ Ahi, const __nv_bfloat16* __restrict__ Alo,
        const __nv_bfloat16* __restrict__ Bhi, const __nv_bfloat16* __restrict__ Blo,
        const float* __restrict__ bias, float* __restrict__ out0,
        float* __restrict__ out1, int mode)
{
    __shared__ __align__(16) char smem[2 * STG];
    const uint32_t sb = smem_u32(smem);
    const int tid = threadIdx.x, wid = tid >> 5, lane = tid & 31;
    const int m0 = blockIdx.y * 128, n0 = blockIdx.x * 128;
    const int wm = wid & 1, wn = wid >> 1;        // warp tile: 64(m) x 32(n)

    // global loader: thread -> row lr, chunk lc (16 bf16 rows, 2 chunks of 8)
    const int lr = tid >> 1, lc = tid & 1;
    const uint32_t soff = tswz(lr, lc);
    const __nv_bfloat16* gAh = Ahi + (size_t)(m0 + lr) * CDIM + lc * 8;
    const __nv_bfloat16* gAl = Alo + (size_t)(m0 + lr) * CDIM + lc * 8;
    const __nv_bfloat16* gBh = Bhi + (size_t)(n0 + lr) * CDIM + lc * 8;
    const __nv_bfloat16* gBl = Blo + (size_t)(n0 + lr) * CDIM + lc * 8;

    // ldmatrix lane addresses (offsets within a tile)
    uint32_t aoff[4], boff[2];
#pragma unroll
    for (int mf = 0; mf < 4; mf++) {
        int r = wm * 64 + mf * 16 + (lane & 7) + ((lane >> 3) & 1) * 8;
        aoff[mf] = tswz(r, lane >> 4);
    }
#pragma unroll
    for (int g = 0; g < 2; g++) {
        int r = wn * 32 + g * 16 + ((lane >> 4) & 1) * 8 + (lane & 7);
        boff[g] = tswz(r, (lane >> 3) & 1);
    }

    float acc[4][4][4];
#pragma unroll
    for (int i = 0; i < 4; i++)
#pragma unroll
        for (int j = 0; j < 4; j++)
#pragma unroll
            for (int v = 0; v < 4; v++) acc[i][j][v] = 0.f;

    // prologue: stage 0
    {
        uint4 va = *(const uint4*)gAh, vb = *(const uint4*)gAl;
        uint4 vc = *(const uint4*)gBh, vd = *(const uint4*)gBl;
        sts128(sb + soff, va);
        sts128(sb + 4096 + soff, vb);
        sts128(sb + 8192 + soff, vc);
        sts128(sb + 12288 + soff, vd);
    }
    __syncthreads();

    for (int kt = 0; kt < 48; kt++) {
        uint4 va, vb, vc, vd;
        if (kt < 47) {
            const int ko = (kt + 1) * 16;
            va = *(const uint4*)(gAh + ko);
            vb = *(const uint4*)(gAl + ko);
            vc = *(const uint4*)(gBh + ko);
            vd = *(const uint4*)(gBl + ko);
        }
        const uint32_t cur = sb + (kt & 1) * STG;

        // B fragments for this k-step (n32: 2 groups of n16)
        uint32_t bh[8], bl[8];
        ldm_x4(bh,     cur + 8192  + boff[0]);
        ldm_x4(bh + 4, cur + 8192  + boff[1]);
        ldm_x4(bl,     cur + 12288 + boff[0]);
        ldm_x4(bl + 4, cur + 12288 + boff[1]);

#pragma unroll
        for (int mf = 0; mf < 4; mf++) {
            uint32_t ah[4], al[4];
            ldm_x4(ah, cur + aoff[mf]);
            ldm_x4(al, cur + 4096 + aoff[mf]);
#pragma unroll
            for (int nf = 0; nf < 4; nf++) {
                const uint32_t* ph = &bh[(nf >> 1) * 4 + (nf & 1) * 2];
                const uint32_t* pl = &bl[(nf >> 1) * 4 + (nf & 1) * 2];
                mma16816(acc[mf][nf], ah, ph);
                mma16816(acc[mf][nf], ah, pl);
                mma16816(acc[mf][nf], al, ph);
            }
        }
        if (kt < 47) {
            __syncthreads();
            const uint32_t nxt = sb + ((kt + 1) & 1) * STG;
            sts128(nxt + soff, va);
            sts128(nxt + 4096 + soff, vb);
            sts128(nxt + 8192 + soff, vc);
            sts128(nxt + 12288 + soff, vd);
            __syncthreads();
        }
    }

    // epilogue
#pragma unroll
    for (int mf = 0; mf < 4; mf++) {
#pragma unroll
        for (int nf = 0; nf < 4; nf++) {
            const int col = n0 + wn * 32 + nf * 8 + (lane & 3) * 2;
            const int r1 = m0 + wm * 64 + mf * 16 + (lane >> 2);
            const float2 bb = *(const float2*)(bias + col);
            float2 v0 = make_float2(acc[mf][nf][0] + bb.x, acc[mf][nf][1] + bb.y);
            float2 v1 = make_float2(acc[mf][nf][2] + bb.x, acc[mf][nf][3] + bb.y);
            if (mode == 0) {
                *(float2*)(out0 + (size_t)r1 * CDIM + col) = v0;
                *(float2*)(out0 + (size_t)(r1 + 8) * CDIM + col) = v1;
            } else {
                const int t = col / CDIM, rem = col - t * CDIM;
                const int h = rem >> 6, d = rem & 63;
                float* dst = (t == 0) ? out0 : (t == 1) ? out1 : out1 + KV_ELEMS;
#pragma unroll
                for (int rr = 0; rr < 2; rr++) {
                    const int row = r1 + rr * 8;
                    const int b = row >> 10, n = row & (NTOK - 1);
                    const size_t idx = ((size_t)(b * NH + h) << 16) | ((size_t)n << 6) | (size_t)d;
                    *(float2*)(dst + idx) = rr ? v1 : v0;
                }
            }
        }
    }
}

// ---------------------------------------------------------------------------
// Kernel 2: rel-pos projections (fp32)
// ---------------------------------------------------------------------------
__global__ void __launch_bounds__(256) rel_kernel(
        const float* __restrict__ rph, const float* __restrict__ rpw)
{
    extern __shared__ float sm[];
    float (*Qs)[68] = (float (*)[68])sm;
    float (*Th)[68] = (float (*)[68])(sm + 64 * 68);
    float (*Tw)[68] = (float (*)[68])(sm + (64 + 63) * 68);

    const int bh = blockIdx.y;
    const int q0 = blockIdx.x * 64;
    const int tid = threadIdx.x;

    for (int i = tid; i < 64 * 16; i += 256) {
        int r = i >> 4, c = (i & 15) << 2;
        float4 v = *(const float4*)(g_Q + ((size_t)(bh * NTOK + q0 + r) << 6) + c);
        Qs[r][c] = v.x; Qs[r][c + 1] = v.y; Qs[r][c + 2] = v.z; Qs[r][c + 3] = v.w;
    }
    for (int i = tid; i < 63 * 16; i += 256) {
        int r = i >> 4, c = (i & 15) << 2;
        float4 vh = *(const float4*)(rph + r * 64 + c);
        Th[r][c] = vh.x; Th[r][c + 1] = vh.y; Th[r][c + 2] = vh.z; Th[r][c + 3] = vh.w;
        float4 vw = *(const float4*)(rpw + r * 64 + c);
        Tw[r][c] = vw.x; Tw[r][c + 1] = vw.y; Tw[r][c + 2] = vw.z; Tw[r][c + 3] = vw.w;
    }
    __syncthreads();

    const int ql = tid >> 2, j4 = tid & 3;
    const int q = q0 + ql, qh = q >> 5, qw = q & 31;
    float* outp = g_REL + ((size_t)(bh * NTOK + q) << 6);
#pragma unroll
    for (int jj = 0; jj < 16; jj++) {
        int j = j4 * 16 + jj;
        const float* T = (j < 32) ? &Th[qh - j + 31][0]
                                  : &Tw[qw - (j - 32) + 31][0];
        float s = 0.f;
#pragma unroll
        for (int d0 = 0; d0 < 64; d0 += 4) {
            float4 qv = *(const float4*)&Qs[ql][d0];
            float4 tv = *(const float4*)(T + d0);
            s += qv.x * tv.x + qv.y * tv.y + qv.z * tv.z + qv.w * tv.w;
        }
        outp[j] = s;
    }
}

// ---------------------------------------------------------------------------
// Kernel 3: fused flash attention with decomposed bias (fp32)
// ---------------------------------------------------------------------------
#define SM_TILE (64 * 68)

__global__ void __launch_bounds__(256) attn_kernel(const float* __restrict__ KV)
{
    extern __shared__ float sm[];
    float (*Qs)[68] = (float (*)[68])sm;
    float (*Ks)[68] = (float (*)[68])(sm + SM_TILE);
    float (*Vs)[68] = (float (*)[68])(sm + 2 * SM_TILE);
    float (*Ps)[68] = (float (*)[68])(sm + 3 * SM_TILE);
    float (*Rs)[68] = (float (*)[68])(sm + 4 * SM_TILE);

    const int bh = blockIdx.y;
    const int q0 = blockIdx.x * 64;
    const int tid = threadIdx.x;
    const int qg = tid >> 3;
    const int tx = tid & 7;

    for (int i = tid; i < 64 * 16; i += 256) {
        int r = i >> 4, c = (i & 15) << 2;
        size_t base = ((size_t)(bh * NTOK + q0 + r) << 6) + c;
        float4 qv = *(const float4*)(g_Q + base);
        Qs[r][c] = qv.x; Qs[r][c + 1] = qv.y; Qs[r][c + 2] = qv.z; Qs[r][c + 3] = qv.w;
        float4 rv = *(const float4*)(g_REL + base);
        Rs[r][c] = rv.x; Rs[r][c + 1] = rv.y; Rs[r][c + 2] = rv.z; Rs[r][c + 3] = rv.w;
    }

    float acc[2][8];
#pragma unroll
    for (int r = 0; r < 2; r++)
#pragma unroll
        for (int j = 0; j < 8; j++) acc[r][j] = 0.f;
    float m_i[2] = {-1e30f, -1e30f};
    float l_i[2] = {0.f, 0.f};

    const float scale = 0.125f;
    const float* Kbase = KV + ((size_t)bh * NTOK << 6);
    const float* Vbase = KV + (size_t)KV_ELEMS + ((size_t)bh * NTOK << 6);

    for (int t = 0; t < 16; t++) {
        const int k0 = t * 64;
        __syncthreads();
        for (int i = tid; i < 64 * 16; i += 256) {
            int r = i >> 4, c = (i & 15) << 2;
            float4 kv4 = *(const float4*)(Kbase + ((size_t)(k0 + r) << 6) + c);
            Ks[r][c] = kv4.x; Ks[r][c + 1] = kv4.y; Ks[r][c + 2] = kv4.z; Ks[r][c + 3] = kv4.w;
            float4 vv4 = *(const float4*)(Vbase + ((size_t)(k0 + r) << 6) + c);
            Vs[r][c] = vv4.x; Vs[r][c + 1] = vv4.y; Vs[r][c + 2] = vv4.z; Vs[r][c + 3] = vv4.w;
        }
        __syncthreads();

        float s[2][8];
#pragma unroll
        for (int r = 0; r < 2; r++)
#pragma unroll
            for (int j = 0; j < 8; j++) s[r][j] = 0.f;

#pragma unroll
        for (int d0 = 0; d0 < 64; d0 += 4) {
            float4 q0v = *(const float4*)&Qs[qg][d0];
            float4 q1v = *(const float4*)&Qs[qg + 32][d0];
#pragma unroll
            for (int jj = 0; jj < 8; jj++) {
                float4 kv4 = *(const float4*)&Ks[jj * 8 + tx][d0];
                s[0][jj] += q0v.x * kv4.x + q0v.y * kv4.y + q0v.z * kv4.z + q0v.w * kv4.w;
                s[1][jj] += q1v.x * kv4.x + q1v.y * kv4.y + q1v.z * kv4.z + q1v.w * kv4.w;
            }
        }

        const int khb = t * 2;
#pragma unroll
        for (int r = 0; r < 2; r++) {
            const int qrow = qg + r * 32;
            float mt = -1e30f;
#pragma unroll
            for (int jj = 0; jj < 8; jj++) {
                int j = jj * 8 + tx;
                float v = s[r][jj] * scale
                        + Rs[qrow][khb + (j >> 5)]
                        + Rs[qrow][32 + (j & 31)];
                s[r][jj] = v;
                mt = fmaxf(mt, v);
            }
            mt = fmaxf(mt, __shfl_xor_sync(0xffffffffu, mt, 1));
            mt = fmaxf(mt, __shfl_xor_sync(0xffffffffu, mt, 2));
            mt = fmaxf(mt, __shfl_xor_sync(0xffffffffu, mt, 4));
            float m_new = fmaxf(m_i[r], mt);
            float alpha = __expf(m_i[r] - m_new);
            float psum = 0.f;
#pragma unroll
            for (int jj = 0; jj < 8; jj++) {
                float p = __expf(s[r][jj] - m_new);
                psum += p;
                Ps[qrow][jj * 8 + tx] = p;
            }
            psum += __shfl_xor_sync(0xffffffffu, psum, 1);
            psum += __shfl_xor_sync(0xffffffffu, psum, 2);
            psum += __shfl_xor_sync(0xffffffffu, psum, 4);
            l_i[r] = l_i[r] * alpha + psum;
            m_i[r] = m_new;
#pragma unroll
            for (int j = 0; j < 8; j++) acc[r][j] *= alpha;
        }
        __syncwarp();

#pragma unroll 4
        for (int k = 0; k < 64; k++) {
            float p0 = Ps[qg][k];
            float p1 = Ps[qg + 32][k];
            float4 va = *(const float4*)&Vs[k][tx * 8];
            float4 vb = *(const float4*)&Vs[k][tx * 8 + 4];
            acc[0][0] += p0 * va.x; acc[0][1] += p0 * va.y;
            acc[0][2] += p0 * va.z; acc[0][3] += p0 * va.w;
            acc[0][4] += p0 * vb.x; acc[0][5] += p0 * vb.y;
            acc[0][6] += p0 * vb.z; acc[0][7] += p0 * vb.w;
            acc[1][0] += p1 * va.x; acc[1][1] += p1 * va.y;
            acc[1][2] += p1 * va.z; acc[1][3] += p1 * va.w;
            acc[1][4] += p1 * vb.x; acc[1][5] += p1 * vb.y;
            acc[1][6] += p1 * vb.z; acc[1][7] += p1 * vb.w;
        }
    }

    const int b = bh / NH, h = bh - b * NH;
#pragma unroll
    for (int r = 0; r < 2; r++) {
        float inv = 1.f / l_i[r];
        int qrow = q0 + qg + r * 32;
        float* op = g_AO + (size_t)(b * NTOK + qrow) * CDIM + h * HD + tx * 8;
        float4 o0 = make_float4(acc[r][0] * inv, acc[r][1] * inv,
                                acc[r][2] * inv, acc[r][3] * inv);
        float4 o1 = make_float4(acc[r][4] * inv, acc[r][5] * inv,
                                acc[r][6] * inv, acc[r][7] * inv);
        *(float4*)op = o0;
        *(float4*)(op + 4) = o1;
    }
}

// ---------------------------------------------------------------------------
extern "C" void kernel_launch(void* const* d_in, const int* in_sizes, int n_in,
                              void* d_out, int out_size)
{
    (void)in_sizes; (void)n_in; (void)out_size;
    const float* x      = (const float*)d_in[0];
    const float* qkv_w  = (const float*)d_in[1];
    const float* qkv_b  = (const float*)d_in[2];
    const float* proj_w = (const float*)d_in[3];
    const float* proj_b = (const float*)d_in[4];
    const float* rph    = (const float*)d_in[5];
    const float* rpw    = (const float*)d_in[6];
    float* out = (float*)d_out;
    float* kv  = out + OUT_ELEMS;   // pre_kv region: K half then V half

    static void *pXhi, *pXlo, *pWqhi, *pWqlo, *pWphi, *pWplo, *pAOhi, *pAOlo,
                *pQ, *pAO;
    cudaGetSymbolAddress(&pXhi, g_Xhi);   cudaGetSymbolAddress(&pXlo, g_Xlo);
    cudaGetSymbolAddress(&pWqhi, g_Wqhi); cudaGetSymbolAddress(&pWqlo, g_Wqlo);
    cudaGetSymbolAddress(&pWphi, g_Wphi); cudaGetSymbolAddress(&pWplo, g_Wplo);
    cudaGetSymbolAddress(&pAOhi, g_AOhi); cudaGetSymbolAddress(&pAOlo, g_AOlo);
    cudaGetSymbolAddress(&pQ, g_Q);       cudaGetSymbolAddress(&pAO, g_AO);

    cudaFuncSetAttribute(rel_kernel,  cudaFuncAttributeMaxDynamicSharedMemorySize,
                         (64 + 63 + 63) * 68 * 4);
    cudaFuncSetAttribute(attn_kernel, cudaFuncAttributeMaxDynamicSharedMemorySize,
                         5 * SM_TILE * 4);

    cvt_hilo<<<OUT_ELEMS / 1024, 256>>>(x, (__nv_bfloat16*)pXhi, (__nv_bfloat16*)pXlo, OUT_ELEMS);
    cvt_hilo<<<(3 * CDIM * CDIM) / 1024, 256>>>(qkv_w, (__nv_bfloat16*)pWqhi,
                                                (__nv_bfloat16*)pWqlo, 3 * CDIM * CDIM);
    cvt_hilo<<<(CDIM * CDIM) / 1024, 256>>>(proj_w, (__nv_bfloat16*)pWphi,
                                            (__nv_bfloat16*)pWplo, CDIM * CDIM);

    gemm_mma<<<dim3(18, 64), 256>>>(
        (const __nv_bfloat16*)pXhi, (const __nv_bfloat16*)pXlo,
        (const __nv_bfloat16*)pWqhi, (const __nv_bfloat16*)pWqlo,
        qkv_b, (float*)pQ, kv, 1);

    rel_kernel<<<dim3(16, 96), 256, (64 + 63 + 63) * 68 * 4>>>(rph, rpw);
    attn_kernel<<<dim3(16, 96), 256, 5 * SM_TILE * 4>>>(kv);

    cvt_hilo<<<OUT_ELEMS / 1024, 256>>>((const float*)pAO, (__nv_bfloat16*)pAOhi,
                                        (__nv_bfloat16*)pAOlo, OUT_ELEMS);

    gemm_mma<<<dim3(6, 64), 256>>>(
        (const __nv_bfloat16*)pAOhi, (const __nv_bfloat16*)pAOlo,
        (const __nv_bfloat16*)pWphi, (const __nv_bfloat16*)pWplo,
        proj_b, out, nullptr, 0);
}

// round 5
// speedup vs baseline: 2.7060x; 2.0606x over previous
#include <cuda_runtime.h>
#include <cuda_bf16.h>
#include <cstdint>

#define NTOK 1024
#define CDIM 768
#define NH   12
#define HD   64
#define NB   8
#define BHN  (NB*NH)               /* 96  */
#define KV_ELEMS (BHN*NTOK*HD)     /* 6291456 */
#define OUT_ELEMS (NB*NTOK*CDIM)   /* 6291456 */

__device__ float g_Q[KV_ELEMS];     // unscaled q fp32 (for rel bias)
__device__ float g_REL[KV_ELEMS];   // per (bh,n): [0,32)=rel_h, [32,64)=rel_w

// bf16 hi/lo split buffers
__device__ __nv_bfloat16 g_Xhi[OUT_ELEMS],  g_Xlo[OUT_ELEMS];
__device__ __nv_bfloat16 g_Wqhi[3*CDIM*CDIM], g_Wqlo[3*CDIM*CDIM];
__device__ __nv_bfloat16 g_Wphi[CDIM*CDIM], g_Wplo[CDIM*CDIM];
__device__ __nv_bfloat16 g_AOhi[OUT_ELEMS], g_AOlo[OUT_ELEMS];
__device__ __nv_bfloat16 g_Qhi[KV_ELEMS], g_Qlo[KV_ELEMS];   // scaled by 0.125
__device__ __nv_bfloat16 g_Khi[KV_ELEMS], g_Klo[KV_ELEMS];
__device__ __nv_bfloat16 g_Vhi[KV_ELEMS], g_Vlo[KV_ELEMS];

// single dynamic smem symbol shared by all kernels
extern __shared__ __align__(16) char dyn_sm[];

// ---------------------------------------------------------------------------
__device__ __forceinline__ uint32_t smem_u32(const void* p) {
    uint32_t a;
    asm("{ .reg .u64 t; cvta.to.shared.u64 t, %1; cvt.u32.u64 %0, t; }" : "=r"(a) : "l"(p));
    return a;
}
__device__ __forceinline__ void ldm_x4(uint32_t* r, uint32_t addr) {
    asm volatile("ldmatrix.sync.aligned.m8n8.x4.shared.b16 {%0,%1,%2,%3}, [%4];"
                 : "=r"(r[0]), "=r"(r[1]), "=r"(r[2]), "=r"(r[3]) : "r"(addr));
}
__device__ __forceinline__ void ldm_x4t(uint32_t* r, uint32_t addr) {
    asm volatile("ldmatrix.sync.aligned.m8n8.x4.trans.shared.b16 {%0,%1,%2,%3}, [%4];"
                 : "=r"(r[0]), "=r"(r[1]), "=r"(r[2]), "=r"(r[3]) : "r"(addr));
}
__device__ __forceinline__ void mma16816(float* d, const uint32_t* a, const uint32_t* b) {
    asm volatile(
        "mma.sync.aligned.m16n8k16.row.col.f32.bf16.bf16.f32 "
        "{%0,%1,%2,%3}, {%4,%5,%6,%7}, {%8,%9}, {%0,%1,%2,%3};"
        : "+f"(d[0]), "+f"(d[1]), "+f"(d[2]), "+f"(d[3])
        : "r"(a[0]), "r"(a[1]), "r"(a[2]), "r"(a[3]), "r"(b[0]), "r"(b[1]));
}
__device__ __forceinline__ void sts128(uint32_t addr, uint4 v) {
    asm volatile("st.shared.v4.b32 [%0], {%1, %2, %3, %4};"
                 :: "r"(addr), "r"(v.x), "r"(v.y), "r"(v.z), "r"(v.w) : "memory");
}
// 32B-row swizzle (gemm tiles)
__device__ __forceinline__ uint32_t tswz(int r, int c) {
    return (uint32_t)(r * 32 + 16 * (c ^ ((r >> 2) & 1)));
}
// 128B-row swizzle (attention tiles): 8 chunks of 16B per row
__device__ __forceinline__ uint32_t a128(int r, int c) {
    return (uint32_t)(r * 128 + 16 * (c ^ (r & 7)));
}
// pack (lo, hi) floats -> bf16x2
__device__ __forceinline__ uint32_t pack_bf16(float lo, float hi) {
    uint32_t r;
    asm("cvt.rn.bf16x2.f32 %0, %1, %2;" : "=r"(r) : "f"(hi), "f"(lo));
    return r;
}
__device__ __forceinline__ float lo_f(uint32_t h) { return __uint_as_float(h << 16); }
__device__ __forceinline__ float hi_f(uint32_t h) { return __uint_as_float(h & 0xFFFF0000u); }

// fast exp on the FMA pipe (no MUFU): 2^n * poly(frac), rel err ~2e-6
__device__ __forceinline__ float fexp(float x) {
    x = fmaxf(x, -80.f);
    float y = x * 1.4426950408889634f;
    float r = y + 12582912.f;
    float n = r - 12582912.f;
    float f = y - n;
    uint32_t i = __float_as_uint(r);
    float s = __uint_as_float((i + (uint32_t)(127 - 0x4B400000)) << 23);
    float p = 0.00133335581f;
    p = fmaf(p, f, 0.00961812911f);
    p = fmaf(p, f, 0.0555041087f);
    p = fmaf(p, f, 0.240226507f);
    p = fmaf(p, f, 0.69314718056f);
    p = fmaf(p, f, 1.0f);
    return s * p;
}

// ---------------------------------------------------------------------------
// Conversion: fp32 -> (bf16 hi, bf16 lo residual)
// ---------------------------------------------------------------------------
__global__ void __launch_bounds__(256) cvt_hilo(
        const float* __restrict__ src, __nv_bfloat16* __restrict__ hi,
        __nv_bfloat16* __restrict__ lo, int n)
{
    int i = (blockIdx.x * 256 + threadIdx.x) * 4;
    if (i >= n) return;
    float4 v = *(const float4*)(src + i);
    uint32_t h0 = pack_bf16(v.x, v.y), h1 = pack_bf16(v.z, v.w);
    uint32_t l0 = pack_bf16(v.x - lo_f(h0), v.y - hi_f(h0));
    uint32_t l1 = pack_bf16(v.z - lo_f(h1), v.w - hi_f(h1));
    ((uint32_t*)(hi + i))[0] = h0; ((uint32_t*)(hi + i))[1] = h1;
    ((uint32_t*)(lo + i))[0] = l0; ((uint32_t*)(lo + i))[1] = l1;
}

// ---------------------------------------------------------------------------
// HMMA bf16x3 GEMM: D(128x128 tile) = A(M,768) @ B(N,768)^T + bias
// mode 0: out0[row*768+col];  mode 1: qkv scatter + hi/lo split outputs.
// ---------------------------------------------------------------------------
#define STG 16384

__global__ void __launch_bounds__(256, 2) gemm_mma(
        const __nv_bfloat16* __restrict__ Ahi, const __nv_bfloat16* __restrict__ Alo,
        const __nv_bfloat16* __restrict__ Bhi, const __nv_bfloat16* __restrict__ Blo,
        const float* __restrict__ bias, float* __restrict__ out0,
        float* __restrict__ out1, int mode)
{
    __shared__ __align__(16) char smem[2 * STG];
    const uint32_t sb = smem_u32(smem);
    const int tid = threadIdx.x, wid = tid >> 5, lane = tid & 31;
    const int m0 = blockIdx.y * 128, n0 = blockIdx.x * 128;
    const int wm = wid & 1, wn = wid >> 1;

    const int lr = tid >> 1, lc = tid & 1;
    const uint32_t soff = tswz(lr, lc);
    const __nv_bfloat16* gAh = Ahi + (size_t)(m0 + lr) * CDIM + lc * 8;
    const __nv_bfloat16* gAl = Alo + (size_t)(m0 + lr) * CDIM + lc * 8;
    const __nv_bfloat16* gBh = Bhi + (size_t)(n0 + lr) * CDIM + lc * 8;
    const __nv_bfloat16* gBl = Blo + (size_t)(n0 + lr) * CDIM + lc * 8;

    uint32_t aoff[4], boff[2];
#pragma unroll
    for (int mf = 0; mf < 4; mf++) {
        int r = wm * 64 + mf * 16 + (lane & 7) + ((lane >> 3) & 1) * 8;
        aoff[mf] = tswz(r, lane >> 4);
    }
#pragma unroll
    for (int g = 0; g < 2; g++) {
        int r = wn * 32 + g * 16 + ((lane >> 4) & 1) * 8 + (lane & 7);
        boff[g] = tswz(r, (lane >> 3) & 1);
    }

    float acc[4][4][4];
#pragma unroll
    for (int i = 0; i < 4; i++)
#pragma unroll
        for (int j = 0; j < 4; j++)
#pragma unroll
            for (int v = 0; v < 4; v++) acc[i][j][v] = 0.f;

    {
        uint4 va = *(const uint4*)gAh, vb = *(const uint4*)gAl;
        uint4 vc = *(const uint4*)gBh, vd = *(const uint4*)gBl;
        sts128(sb + soff, va);
        sts128(sb + 4096 + soff, vb);
        sts128(sb + 8192 + soff, vc);
        sts128(sb + 12288 + soff, vd);
    }
    __syncthreads();

    for (int kt = 0; kt < 48; kt++) {
        uint4 va, vb, vc, vd;
        if (kt < 47) {
            const int ko = (kt + 1) * 16;
            va = *(const uint4*)(gAh + ko);
            vb = *(const uint4*)(gAl + ko);
            vc = *(const uint4*)(gBh + ko);
            vd = *(const uint4*)(gBl + ko);
        }
        const uint32_t cur = sb + (kt & 1) * STG;

        uint32_t bh[8], bl[8];
        ldm_x4(bh,     cur + 8192  + boff[0]);
        ldm_x4(bh + 4, cur + 8192  + boff[1]);
        ldm_x4(bl,     cur + 12288 + boff[0]);
        ldm_x4(bl + 4, cur + 12288 + boff[1]);

#pragma unroll
        for (int mf = 0; mf < 4; mf++) {
            uint32_t ah[4], al[4];
            ldm_x4(ah, cur + aoff[mf]);
            ldm_x4(al, cur + 4096 + aoff[mf]);
#pragma unroll
            for (int nf = 0; nf < 4; nf++) {
                const uint32_t* ph = &bh[(nf >> 1) * 4 + (nf & 1) * 2];
                const uint32_t* pl = &bl[(nf >> 1) * 4 + (nf & 1) * 2];
                mma16816(acc[mf][nf], ah, ph);
                mma16816(acc[mf][nf], ah, pl);
                mma16816(acc[mf][nf], al, ph);
            }
        }
        if (kt < 47) {
            __syncthreads();
            const uint32_t nxt = sb + ((kt + 1) & 1) * STG;
            sts128(nxt + soff, va);
            sts128(nxt + 4096 + soff, vb);
            sts128(nxt + 8192 + soff, vc);
            sts128(nxt + 12288 + soff, vd);
            __syncthreads();
        }
    }

#pragma unroll
    for (int mf = 0; mf < 4; mf++) {
#pragma unroll
        for (int nf = 0; nf < 4; nf++) {
            const int col = n0 + wn * 32 + nf * 8 + (lane & 3) * 2;
            const int r1 = m0 + wm * 64 + mf * 16 + (lane >> 2);
            const float2 bb = *(const float2*)(bias + col);
            float2 v0 = make_float2(acc[mf][nf][0] + bb.x, acc[mf][nf][1] + bb.y);
            float2 v1 = make_float2(acc[mf][nf][2] + bb.x, acc[mf][nf][3] + bb.y);
            if (mode == 0) {
                *(float2*)(out0 + (size_t)r1 * CDIM + col) = v0;
                *(float2*)(out0 + (size_t)(r1 + 8) * CDIM + col) = v1;
            } else {
                const int t = col / CDIM, rem = col - t * CDIM;
                const int h = rem >> 6, d = rem & 63;
                float* dst = (t == 0) ? out0 : (t == 1) ? out1 : out1 + KV_ELEMS;
                __nv_bfloat16* hib = (t == 0) ? g_Qhi : (t == 1) ? g_Khi : g_Vhi;
                __nv_bfloat16* lob = (t == 0) ? g_Qlo : (t == 1) ? g_Klo : g_Vlo;
                const float sc = (t == 0) ? 0.125f : 1.f;
#pragma unroll
                for (int rr = 0; rr < 2; rr++) {
                    const int row = r1 + rr * 8;
                    const int b = row >> 10, n = row & (NTOK - 1);
                    const size_t idx = ((size_t)(b * NH + h) << 16) | ((size_t)n << 6) | (size_t)d;
                    float2 vv = rr ? v1 : v0;
                    *(float2*)(dst + idx) = vv;
                    float sx = vv.x * sc, sy = vv.y * sc;
                    uint32_t hh = pack_bf16(sx, sy);
                    uint32_t ll = pack_bf16(sx - lo_f(hh), sy - hi_f(hh));
                    *(uint32_t*)(hib + idx) = hh;
                    *(uint32_t*)(lob + idx) = ll;
                }
            }
        }
    }
}

// ---------------------------------------------------------------------------
// rel-pos projections (fp32)
// ---------------------------------------------------------------------------
__global__ void __launch_bounds__(256) rel_kernel(
        const float* __restrict__ rph, const float* __restrict__ rpw)
{
    float* smf = (float*)dyn_sm;
    float (*Qs)[68] = (float (*)[68])smf;
    float (*Th)[68] = (float (*)[68])(smf + 64 * 68);
    float (*Tw)[68] = (float (*)[68])(smf + (64 + 63) * 68);

    const int bh = blockIdx.y;
    const int q0 = blockIdx.x * 64;
    const int tid = threadIdx.x;

    for (int i = tid; i < 64 * 16; i += 256) {
        int r = i >> 4, c = (i & 15) << 2;
        float4 v = *(const float4*)(g_Q + ((size_t)(bh * NTOK + q0 + r) << 6) + c);
        Qs[r][c] = v.x; Qs[r][c + 1] = v.y; Qs[r][c + 2] = v.z; Qs[r][c + 3] = v.w;
    }
    for (int i = tid; i < 63 * 16; i += 256) {
        int r = i >> 4, c = (i & 15) << 2;
        float4 vh = *(const float4*)(rph + r * 64 + c);
        Th[r][c] = vh.x; Th[r][c + 1] = vh.y; Th[r][c + 2] = vh.z; Th[r][c + 3] = vh.w;
        float4 vw = *(const float4*)(rpw + r * 64 + c);
        Tw[r][c] = vw.x; Tw[r][c + 1] = vw.y; Tw[r][c + 2] = vw.z; Tw[r][c + 3] = vw.w;
    }
    __syncthreads();

    const int ql = tid >> 2, j4 = tid & 3;
    const int q = q0 + ql, qh = q >> 5, qw = q & 31;
    float* outp = g_REL + ((size_t)(bh * NTOK + q) << 6);
#pragma unroll
    for (int jj = 0; jj < 16; jj++) {
        int j = j4 * 16 + jj;
        const float* T = (j < 32) ? &Th[qh - j + 31][0]
                                  : &Tw[qw - (j - 32) + 31][0];
        float s = 0.f;
#pragma unroll
        for (int d0 = 0; d0 < 64; d0 += 4) {
            float4 qv = *(const float4*)&Qs[ql][d0];
            float4 tv = *(const float4*)(T + d0);
            s += qv.x * tv.x + qv.y * tv.y + qv.z * tv.z + qv.w * tv.w;
        }
        outp[j] = s;
    }
}

// ---------------------------------------------------------------------------
// Tensor-core flash attention, bf16x3, poly-exp.
// CTA = (bh, 128-query tile), 8 warps x 16 q rows. K-tiles of 64 keys.
// smem: Qhi 16K | Qlo 16K | Khi 8K | Klo 8K | Vhi 8K | Vlo 8K | REL 32K = 96K
// ---------------------------------------------------------------------------
#define ASM_TOT 98304

__global__ void __launch_bounds__(256, 2) attn_mma()
{
    const uint32_t sb = smem_u32(dyn_sm);
    const uint32_t Qh = sb, Ql = sb + 16384;
    const uint32_t Kh = sb + 32768, Vh = sb + 49152;
    float* RELs = (float*)(dyn_sm + 65536);

    const int bh = blockIdx.y, q0 = blockIdx.x * 128;
    const int tid = threadIdx.x, wid = tid >> 5, lane = tid & 31;

    // load Q hi/lo + REL
    {
        const int row = tid >> 1, half = tid & 1;
        const size_t gb = ((size_t)bh << 16) | ((size_t)(q0 + row) << 6);
        const uint4* qh = (const uint4*)(g_Qhi + gb);
        const uint4* ql = (const uint4*)(g_Qlo + gb);
#pragma unroll
        for (int c = 0; c < 4; c++) {
            const int cc = half * 4 + c;
            sts128(Qh + a128(row, cc), qh[cc]);
            sts128(Ql + a128(row, cc), ql[cc]);
        }
        const float4* rs = (const float4*)(g_REL + gb);
        float4* rd = (float4*)(RELs + row * 64);
#pragma unroll
        for (int c = 0; c < 8; c++) rd[half * 8 + c] = rs[half * 8 + c];
    }
    __syncthreads();

    const int qr = wid * 16;
    const int r0 = qr + (lane >> 2);          // rows r0, r0+8

    // preload rel_w into regs: rw[row][colparity][f&3]
    float rw[2][2][4];
#pragma unroll
    for (int rr = 0; rr < 2; rr++)
#pragma unroll
        for (int c = 0; c < 2; c++)
#pragma unroll
            for (int f4 = 0; f4 < 4; f4++)
                rw[rr][c][f4] = RELs[(r0 + rr * 8) * 64 + 32 + ((lane & 3) * 2 + c + f4 * 8)];

    float O[8][4];
#pragma unroll
    for (int f = 0; f < 8; f++)
#pragma unroll
        for (int v = 0; v < 4; v++) O[f][v] = 0.f;
    float m_[2] = {-1e30f, -1e30f}, l_[2] = {0.f, 0.f};

    for (int t = 0; t < 16; t++) {
        const int k0 = t * 64;
        __syncthreads();
        {   // load K/V hi/lo tiles (64 keys x 64 d each)
            const int arr = tid >> 6, row = tid & 63;
            const __nv_bfloat16* gsrc = (arr == 0) ? g_Khi : (arr == 1) ? g_Klo
                                      : (arr == 2) ? g_Vhi : g_Vlo;
            const uint4* src = (const uint4*)(gsrc + (((size_t)bh << 16) | ((size_t)(k0 + row) << 6)));
            const uint32_t dst = sb + 32768 + arr * 8192;
#pragma unroll
            for (int c = 0; c < 8; c++) sts128(dst + a128(row, c), src[c]);
        }
        __syncthreads();

        float S[8][4];
#pragma unroll
        for (int f = 0; f < 8; f++)
#pragma unroll
            for (int v = 0; v < 4; v++) S[f][v] = 0.f;

#pragma unroll
        for (int ks = 0; ks < 4; ks++) {
            uint32_t ah[4], al[4];
            const uint32_t aaddr = Qh + a128(qr + (lane & 7) + ((lane >> 3) & 1) * 8,
                                             2 * ks + (lane >> 4));
            ldm_x4(ah, aaddr);
            ldm_x4(al, aaddr + 16384);
#pragma unroll
            for (int g = 0; g < 4; g++) {
                uint32_t kb[4], kl[4];
                const uint32_t kaddr = Kh + a128(g * 16 + ((lane >> 4) & 1) * 8 + (lane & 7),
                                                 2 * ks + ((lane >> 3) & 1));
                ldm_x4(kb, kaddr);
                ldm_x4(kl, kaddr + 8192);
                mma16816(S[2*g],   ah, kb);     mma16816(S[2*g],   ah, kl);     mma16816(S[2*g],   al, kb);
                mma16816(S[2*g+1], ah, kb + 2); mma16816(S[2*g+1], ah, kl + 2); mma16816(S[2*g+1], al, kb + 2);
            }
        }

        // bias + online softmax
        const int khb = k0 >> 5;
        float alpha[2];
#pragma unroll
        for (int rr = 0; rr < 2; rr++) {
            const int row = r0 + rr * 8;
            const float rh0 = RELs[row * 64 + khb], rh1 = RELs[row * 64 + khb + 1];
            float mx = m_[rr];
#pragma unroll
            for (int f = 0; f < 8; f++) {
                const float rh = (f < 4) ? rh0 : rh1;
                S[f][rr*2]   += rh + rw[rr][0][f & 3];
                S[f][rr*2+1] += rh + rw[rr][1][f & 3];
                mx = fmaxf(mx, fmaxf(S[f][rr*2], S[f][rr*2+1]));
            }
            mx = fmaxf(mx, __shfl_xor_sync(0xffffffffu, mx, 1));
            mx = fmaxf(mx, __shfl_xor_sync(0xffffffffu, mx, 2));
            alpha[rr] = fexp(m_[rr] - mx);
            m_[rr] = mx;
            float ps = 0.f;
#pragma unroll
            for (int f = 0; f < 8; f++) {
                float p0 = fexp(S[f][rr*2]   - mx);
                float p1 = fexp(S[f][rr*2+1] - mx);
                S[f][rr*2] = p0; S[f][rr*2+1] = p1;
                ps += p0 + p1;
            }
            ps += __shfl_xor_sync(0xffffffffu, ps, 1);
            ps += __shfl_xor_sync(0xffffffffu, ps, 2);
            l_[rr] = l_[rr] * alpha[rr] + ps;
#pragma unroll
            for (int f = 0; f < 8; f++) { O[f][rr*2] *= alpha[rr]; O[f][rr*2+1] *= alpha[rr]; }
        }

        // P repack (hi/lo) + PV MMAs
#pragma unroll
        for (int ks = 0; ks < 4; ks++) {
            uint32_t ph[4], pl[4];
#pragma unroll
            for (int part = 0; part < 4; part++) {
                const int f = 2 * ks + (part >> 1);
                const float x0 = S[f][(part & 1) * 2], x1 = S[f][(part & 1) * 2 + 1];
                uint32_t h = pack_bf16(x0, x1);
                ph[part] = h;
                pl[part] = pack_bf16(x0 - lo_f(h), x1 - hi_f(h));
            }
#pragma unroll
            for (int dg = 0; dg < 4; dg++) {
                uint32_t vb[4], vl[4];
                const uint32_t vaddr = Vh + a128(ks * 16 + ((lane >> 3) & 1) * 8 + (lane & 7),
                                                 2 * dg + (lane >> 4));
                ldm_x4t(vb, vaddr);
                ldm_x4t(vl, vaddr + 8192);
                mma16816(O[2*dg],   ph, vb);     mma16816(O[2*dg],   ph, vl);     mma16816(O[2*dg],   pl, vb);
                mma16816(O[2*dg+1], ph, vb + 2); mma16816(O[2*dg+1], ph, vl + 2); mma16816(O[2*dg+1], pl, vb + 2);
            }
        }
    }

    // epilogue: normalize, split hi/lo, store to g_AOhi/lo
    const float inv0 = 1.f / l_[0], inv1 = 1.f / l_[1];
    const int b = bh / NH, h = bh - b * NH;
#pragma unroll
    for (int f = 0; f < 8; f++) {
        const int col = h * HD + f * 8 + (lane & 3) * 2;
        const size_t i0 = (size_t)(b * NTOK + q0 + r0) * CDIM + col;
        const size_t i1 = (size_t)(b * NTOK + q0 + r0 + 8) * CDIM + col;
        float x0 = O[f][0] * inv0, x1 = O[f][1] * inv0;
        float x2 = O[f][2] * inv1, x3 = O[f][3] * inv1;
        uint32_t h0 = pack_bf16(x0, x1), h1 = pack_bf16(x2, x3);
        *(uint32_t*)(g_AOhi + i0) = h0;
        *(uint32_t*)(g_AOlo + i0) = pack_bf16(x0 - lo_f(h0), x1 - hi_f(h0));
        *(uint32_t*)(g_AOhi + i1) = h1;
        *(uint32_t*)(g_AOlo + i1) = pack_bf16(x2 - lo_f(h1), x3 - hi_f(h1));
    }
}

// ---------------------------------------------------------------------------
extern "C" void kernel_launch(void* const* d_in, const int* in_sizes, int n_in,
                              void* d_out, int out_size)
{
    (void)in_sizes; (void)n_in; (void)out_size;
    const float* x      = (const float*)d_in[0];
    const float* qkv_w  = (const float*)d_in[1];
    const float* qkv_b  = (const float*)d_in[2];
    const float* proj_w = (const float*)d_in[3];
    const float* proj_b = (const float*)d_in[4];
    const float* rph    = (const float*)d_in[5];
    const float* rpw    = (const float*)d_in[6];
    float* out = (float*)d_out;
    float* kv  = out + OUT_ELEMS;

    static void *pXhi, *pXlo, *pWqhi, *pWqlo, *pWphi, *pWplo, *pAOhi, *pAOlo, *pQ;
    cudaGetSymbolAddress(&pXhi, g_Xhi);   cudaGetSymbolAddress(&pXlo, g_Xlo);
    cudaGetSymbolAddress(&pWqhi, g_Wqhi); cudaGetSymbolAddress(&pWqlo, g_Wqlo);
    cudaGetSymbolAddress(&pWphi, g_Wphi); cudaGetSymbolAddress(&pWplo, g_Wplo);
    cudaGetSymbolAddress(&pAOhi, g_AOhi); cudaGetSymbolAddress(&pAOlo, g_AOlo);
    cudaGetSymbolAddress(&pQ, g_Q);

    cudaFuncSetAttribute(rel_kernel, cudaFuncAttributeMaxDynamicSharedMemorySize,
                         (64 + 63 + 63) * 68 * 4);
    cudaFuncSetAttribute(attn_mma, cudaFuncAttributeMaxDynamicSharedMemorySize, ASM_TOT);

    cvt_hilo<<<OUT_ELEMS / 1024, 256>>>(x, (__nv_bfloat16*)pXhi, (__nv_bfloat16*)pXlo, OUT_ELEMS);
    cvt_hilo<<<(3 * CDIM * CDIM) / 1024, 256>>>(qkv_w, (__nv_bfloat16*)pWqhi,
                                                (__nv_bfloat16*)pWqlo, 3 * CDIM * CDIM);
    cvt_hilo<<<(CDIM * CDIM) / 1024, 256>>>(proj_w, (__nv_bfloat16*)pWphi,
                                            (__nv_bfloat16*)pWplo, CDIM * CDIM);

    gemm_mma<<<dim3(18, 64), 256>>>(
        (const __nv_bfloat16*)pXhi, (const __nv_bfloat16*)pXlo,
        (const __nv_bfloat16*)pWqhi, (const __nv_bfloat16*)pWqlo,
        qkv_b, (float*)pQ, kv, 1);

    rel_kernel<<<dim3(16, 96), 256, (64 + 63 + 63) * 68 * 4>>>(rph, rpw);

    attn_mma<<<dim3(8, 96), 256, ASM_TOT>>>();

    gemm_mma<<<dim3(6, 64), 256>>>(
        (const __nv_bfloat16*)pAOhi, (const __nv_bfloat16*)pAOlo,
        (const __nv_bfloat16*)pWphi, (const __nv_bfloat16*)pWplo,
        proj_b, out, nullptr, 0);
}

// round 6
// speedup vs baseline: 2.9277x; 1.0819x over previous
#include <cuda_runtime.h>
#include <cuda_bf16.h>
#include <cstdint>

#define NTOK 1024
#define CDIM 768
#define NH   12
#define HD   64
#define NB   8
#define BHN  (NB*NH)               /* 96  */
#define KV_ELEMS (BHN*NTOK*HD)     /* 6291456 */
#define OUT_ELEMS (NB*NTOK*CDIM)   /* 6291456 */

__device__ float g_Q[KV_ELEMS];     // unscaled q fp32 (for rel bias)
__device__ float g_REL[KV_ELEMS];   // per (bh,n): [0,32)=rel_h, [32,64)=rel_w

// bf16 hi/lo split buffers
__device__ __nv_bfloat16 g_Xhi[OUT_ELEMS],  g_Xlo[OUT_ELEMS];
__device__ __nv_bfloat16 g_Wqhi[3*CDIM*CDIM], g_Wqlo[3*CDIM*CDIM];
__device__ __nv_bfloat16 g_Wphi[CDIM*CDIM], g_Wplo[CDIM*CDIM];
__device__ __nv_bfloat16 g_AOhi[OUT_ELEMS], g_AOlo[OUT_ELEMS];
__device__ __nv_bfloat16 g_Qhi[KV_ELEMS], g_Qlo[KV_ELEMS];   // scaled by 0.125
__device__ __nv_bfloat16 g_Khi[KV_ELEMS], g_Klo[KV_ELEMS];
__device__ __nv_bfloat16 g_Vhi[KV_ELEMS], g_Vlo[KV_ELEMS];

// single dynamic smem symbol shared by all kernels
extern __shared__ __align__(16) char dyn_sm[];

// ---------------------------------------------------------------------------
__device__ __forceinline__ uint32_t smem_u32(const void* p) {
    uint32_t a;
    asm("{ .reg .u64 t; cvta.to.shared.u64 t, %1; cvt.u32.u64 %0, t; }" : "=r"(a) : "l"(p));
    return a;
}
__device__ __forceinline__ void ldm_x4(uint32_t* r, uint32_t addr) {
    asm volatile("ldmatrix.sync.aligned.m8n8.x4.shared.b16 {%0,%1,%2,%3}, [%4];"
                 : "=r"(r[0]), "=r"(r[1]), "=r"(r[2]), "=r"(r[3]) : "r"(addr));
}
__device__ __forceinline__ void ldm_x4t(uint32_t* r, uint32_t addr) {
    asm volatile("ldmatrix.sync.aligned.m8n8.x4.trans.shared.b16 {%0,%1,%2,%3}, [%4];"
                 : "=r"(r[0]), "=r"(r[1]), "=r"(r[2]), "=r"(r[3]) : "r"(addr));
}
__device__ __forceinline__ void mma16816(float* d, const uint32_t* a, const uint32_t* b) {
    asm volatile(
        "mma.sync.aligned.m16n8k16.row.col.f32.bf16.bf16.f32 "
        "{%0,%1,%2,%3}, {%4,%5,%6,%7}, {%8,%9}, {%0,%1,%2,%3};"
        : "+f"(d[0]), "+f"(d[1]), "+f"(d[2]), "+f"(d[3])
        : "r"(a[0]), "r"(a[1]), "r"(a[2]), "r"(a[3]), "r"(b[0]), "r"(b[1]));
}
__device__ __forceinline__ void sts128(uint32_t addr, uint4 v) {
    asm volatile("st.shared.v4.b32 [%0], {%1, %2, %3, %4};"
                 :: "r"(addr), "r"(v.x), "r"(v.y), "r"(v.z), "r"(v.w) : "memory");
}
__device__ __forceinline__ void cp16(uint32_t dst, const void* src) {
    asm volatile("cp.async.cg.shared.global [%0], [%1], 16;" :: "r"(dst), "l"(src));
}
#define CP_COMMIT asm volatile("cp.async.commit_group;" ::: "memory")
#define CP_WAIT0  asm volatile("cp.async.wait_group 0;" ::: "memory")

// 32B-row swizzle (gemm tiles)
__device__ __forceinline__ uint32_t tswz(int r, int c) {
    return (uint32_t)(r * 32 + 16 * (c ^ ((r >> 2) & 1)));
}
// 128B-row swizzle (attention tiles): 8 chunks of 16B per row
__device__ __forceinline__ uint32_t a128(int r, int c) {
    return (uint32_t)(r * 128 + 16 * (c ^ (r & 7)));
}
// pack (lo, hi) floats -> bf16x2
__device__ __forceinline__ uint32_t pack_bf16(float lo, float hi) {
    uint32_t r;
    asm("cvt.rn.bf16x2.f32 %0, %1, %2;" : "=r"(r) : "f"(hi), "f"(lo));
    return r;
}
__device__ __forceinline__ float lo_f(uint32_t h) { return __uint_as_float(h << 16); }
__device__ __forceinline__ float hi_f(uint32_t h) { return __uint_as_float(h & 0xFFFF0000u); }

// fast exp on the FMA pipe (no MUFU)
__device__ __forceinline__ float fexp(float x) {
    x = fmaxf(x, -80.f);
    float y = x * 1.4426950408889634f;
    float r = y + 12582912.f;
    float n = r - 12582912.f;
    float f = y - n;
    uint32_t i = __float_as_uint(r);
    float s = __uint_as_float((i + (uint32_t)(127 - 0x4B400000)) << 23);
    float p = 0.00133335581f;
    p = fmaf(p, f, 0.00961812911f);
    p = fmaf(p, f, 0.0555041087f);
    p = fmaf(p, f, 0.240226507f);
    p = fmaf(p, f, 0.69314718056f);
    p = fmaf(p, f, 1.0f);
    return s * p;
}

// ---------------------------------------------------------------------------
// Conversion: fp32 -> (bf16 hi, bf16 lo residual)
// ---------------------------------------------------------------------------
__global__ void __launch_bounds__(256) cvt_hilo(
        const float* __restrict__ src, __nv_bfloat16* __restrict__ hi,
        __nv_bfloat16* __restrict__ lo, int n)
{
    int i = (blockIdx.x * 256 + threadIdx.x) * 4;
    if (i >= n) return;
    float4 v = *(const float4*)(src + i);
    uint32_t h0 = pack_bf16(v.x, v.y), h1 = pack_bf16(v.z, v.w);
    uint32_t l0 = pack_bf16(v.x - lo_f(h0), v.y - hi_f(h0));
    uint32_t l1 = pack_bf16(v.z - lo_f(h1), v.w - hi_f(h1));
    ((uint32_t*)(hi + i))[0] = h0; ((uint32_t*)(hi + i))[1] = h1;
    ((uint32_t*)(lo + i))[0] = l0; ((uint32_t*)(lo + i))[1] = l1;
}

// ---------------------------------------------------------------------------
// HMMA bf16x3 GEMM with cp.async 2-stage pipeline.
// D(128x128 tile) = A(M,768) @ B(N,768)^T + bias
// mode 0: out0[row*768+col];  mode 1: qkv scatter + hi/lo split outputs.
// ---------------------------------------------------------------------------
#define STG 16384

__global__ void __launch_bounds__(256, 2) gemm_mma(
        const __nv_bfloat16* __restrict__ Ahi, const __nv_bfloat16* __restrict__ Alo,
        const __nv_bfloat16* __restrict__ Bhi, const __nv_bfloat16* __restrict__ Blo,
        const float* __restrict__ bias, float* __restrict__ out0,
        float* __restrict__ out1, int mode)
{
    __shared__ __align__(16) char smem[2 * STG];
    const uint32_t sb = smem_u32(smem);
    const int tid = threadIdx.x, wid = tid >> 5, lane = tid & 31;
    const int m0 = blockIdx.y * 128, n0 = blockIdx.x * 128;
    const int wm = wid & 1, wn = wid >> 1;

    const int lr = tid >> 1, lc = tid & 1;
    const uint32_t soff = tswz(lr, lc);
    const __nv_bfloat16* gAh = Ahi + (size_t)(m0 + lr) * CDIM + lc * 8;
    const __nv_bfloat16* gAl = Alo + (size_t)(m0 + lr) * CDIM + lc * 8;
    const __nv_bfloat16* gBh = Bhi + (size_t)(n0 + lr) * CDIM + lc * 8;
    const __nv_bfloat16* gBl = Blo + (size_t)(n0 + lr) * CDIM + lc * 8;

    uint32_t aoff[4], boff[2];
#pragma unroll
    for (int mf = 0; mf < 4; mf++) {
        int r = wm * 64 + mf * 16 + (lane & 7) + ((lane >> 3) & 1) * 8;
        aoff[mf] = tswz(r, lane >> 4);
    }
#pragma unroll
    for (int g = 0; g < 2; g++) {
        int r = wn * 32 + g * 16 + ((lane >> 4) & 1) * 8 + (lane & 7);
        boff[g] = tswz(r, (lane >> 3) & 1);
    }

    float acc[4][4][4];
#pragma unroll
    for (int i = 0; i < 4; i++)
#pragma unroll
        for (int j = 0; j < 4; j++)
#pragma unroll
            for (int v = 0; v < 4; v++) acc[i][j][v] = 0.f;

    // prologue: stage 0
    cp16(sb + soff, gAh);
    cp16(sb + 4096 + soff, gAl);
    cp16(sb + 8192 + soff, gBh);
    cp16(sb + 12288 + soff, gBl);
    CP_COMMIT; CP_WAIT0;
    __syncthreads();

    for (int kt = 0; kt < 48; kt++) {
        const uint32_t cur = sb + (kt & 1) * STG;
        if (kt < 47) {
            const uint32_t nxt = sb + ((kt + 1) & 1) * STG;
            const int ko = (kt + 1) * 16;
            cp16(nxt + soff, gAh + ko);
            cp16(nxt + 4096 + soff, gAl + ko);
            cp16(nxt + 8192 + soff, gBh + ko);
            cp16(nxt + 12288 + soff, gBl + ko);
            CP_COMMIT;
        }

        uint32_t bh[8], bl[8];
        ldm_x4(bh,     cur + 8192  + boff[0]);
        ldm_x4(bh + 4, cur + 8192  + boff[1]);
        ldm_x4(bl,     cur + 12288 + boff[0]);
        ldm_x4(bl + 4, cur + 12288 + boff[1]);

#pragma unroll
        for (int mf = 0; mf < 4; mf++) {
            uint32_t ah[4], al[4];
            ldm_x4(ah, cur + aoff[mf]);
            ldm_x4(al, cur + 4096 + aoff[mf]);
#pragma unroll
            for (int nf = 0; nf < 4; nf++) {
                const uint32_t* ph = &bh[(nf >> 1) * 4 + (nf & 1) * 2];
                const uint32_t* pl = &bl[(nf >> 1) * 4 + (nf & 1) * 2];
                mma16816(acc[mf][nf], ah, ph);
                mma16816(acc[mf][nf], ah, pl);
                mma16816(acc[mf][nf], al, ph);
            }
        }
        CP_WAIT0;
        __syncthreads();
    }

#pragma unroll
    for (int mf = 0; mf < 4; mf++) {
#pragma unroll
        for (int nf = 0; nf < 4; nf++) {
            const int col = n0 + wn * 32 + nf * 8 + (lane & 3) * 2;
            const int r1 = m0 + wm * 64 + mf * 16 + (lane >> 2);
            const float2 bb = *(const float2*)(bias + col);
            float2 v0 = make_float2(acc[mf][nf][0] + bb.x, acc[mf][nf][1] + bb.y);
            float2 v1 = make_float2(acc[mf][nf][2] + bb.x, acc[mf][nf][3] + bb.y);
            if (mode == 0) {
                *(float2*)(out0 + (size_t)r1 * CDIM + col) = v0;
                *(float2*)(out0 + (size_t)(r1 + 8) * CDIM + col) = v1;
            } else {
                const int t = col / CDIM, rem = col - t * CDIM;
                const int h = rem >> 6, d = rem & 63;
                float* dst = (t == 0) ? out0 : (t == 1) ? out1 : out1 + KV_ELEMS;
                __nv_bfloat16* hib = (t == 0) ? g_Qhi : (t == 1) ? g_Khi : g_Vhi;
                __nv_bfloat16* lob = (t == 0) ? g_Qlo : (t == 1) ? g_Klo : g_Vlo;
                const float sc = (t == 0) ? 0.125f : 1.f;
#pragma unroll
                for (int rr = 0; rr < 2; rr++) {
                    const int row = r1 + rr * 8;
                    const int b = row >> 10, n = row & (NTOK - 1);
                    const size_t idx = ((size_t)(b * NH + h) << 16) | ((size_t)n << 6) | (size_t)d;
                    float2 vv = rr ? v1 : v0;
                    *(float2*)(dst + idx) = vv;
                    float sx = vv.x * sc, sy = vv.y * sc;
                    uint32_t hh = pack_bf16(sx, sy);
                    uint32_t ll = pack_bf16(sx - lo_f(hh), sy - hi_f(hh));
                    *(uint32_t*)(hib + idx) = hh;
                    *(uint32_t*)(lob + idx) = ll;
                }
            }
        }
    }
}

// ---------------------------------------------------------------------------
// rel-pos projections (fp32)
// ---------------------------------------------------------------------------
__global__ void __launch_bounds__(256) rel_kernel(
        const float* __restrict__ rph, const float* __restrict__ rpw)
{
    float* smf = (float*)dyn_sm;
    float (*Qs)[68] = (float (*)[68])smf;
    float (*Th)[68] = (float (*)[68])(smf + 64 * 68);
    float (*Tw)[68] = (float (*)[68])(smf + (64 + 63) * 68);

    const int bh = blockIdx.y;
    const int q0 = blockIdx.x * 64;
    const int tid = threadIdx.x;

    for (int i = tid; i < 64 * 16; i += 256) {
        int r = i >> 4, c = (i & 15) << 2;
        float4 v = *(const float4*)(g_Q + ((size_t)(bh * NTOK + q0 + r) << 6) + c);
        Qs[r][c] = v.x; Qs[r][c + 1] = v.y; Qs[r][c + 2] = v.z; Qs[r][c + 3] = v.w;
    }
    for (int i = tid; i < 63 * 16; i += 256) {
        int r = i >> 4, c = (i & 15) << 2;
        float4 vh = *(const float4*)(rph + r * 64 + c);
        Th[r][c] = vh.x; Th[r][c + 1] = vh.y; Th[r][c + 2] = vh.z; Th[r][c + 3] = vh.w;
        float4 vw = *(const float4*)(rpw + r * 64 + c);
        Tw[r][c] = vw.x; Tw[r][c + 1] = vw.y; Tw[r][c + 2] = vw.z; Tw[r][c + 3] = vw.w;
    }
    __syncthreads();

    const int ql = tid >> 2, j4 = tid & 3;
    const int q = q0 + ql, qh = q >> 5, qw = q & 31;
    float* outp = g_REL + ((size_t)(bh * NTOK + q) << 6);
#pragma unroll
    for (int jj = 0; jj < 16; jj++) {
        int j = j4 * 16 + jj;
        const float* T = (j < 32) ? &Th[qh - j + 31][0]
                                  : &Tw[qw - (j - 32) + 31][0];
        float s = 0.f;
#pragma unroll
        for (int d0 = 0; d0 < 64; d0 += 4) {
            float4 qv = *(const float4*)&Qs[ql][d0];
            float4 tv = *(const float4*)(T + d0);
            s += qv.x * tv.x + qv.y * tv.y + qv.z * tv.z + qv.w * tv.w;
        }
        outp[j] = s;
    }
}

// ---------------------------------------------------------------------------
// Tensor-core flash attention, bf16x3, poly-exp, cp.async double-buffered K/V.
// smem: Qhi 16K | Qlo 16K | RELh 16K | KV stage0 32K | KV stage1 32K = 112K
// ---------------------------------------------------------------------------
#define ASM_TOT 114688
#define KVB 49152

__global__ void __launch_bounds__(256, 2) attn_mma()
{
    const uint32_t sb = smem_u32(dyn_sm);
    const uint32_t Qh = sb, Ql = sb + 16384;
    float* RELh = (float*)(dyn_sm + 32768);

    const int bh = blockIdx.y, q0 = blockIdx.x * 128;
    const int tid = threadIdx.x, wid = tid >> 5, lane = tid & 31;

    // K/V loader assignment: arr 0..3 -> Khi,Klo,Vhi,Vlo; row 0..63
    const int arr = tid >> 6, krow = tid & 63;
    const __nv_bfloat16* kvsrc = (arr == 0) ? g_Khi : (arr == 1) ? g_Klo
                               : (arr == 2) ? g_Vhi : g_Vlo;
    kvsrc += ((size_t)bh << 16) | ((size_t)krow << 6);

    // prologue: issue K/V tile 0
    {
        const uint32_t dst = sb + KVB + arr * 8192;
#pragma unroll
        for (int c = 0; c < 8; c++) cp16(dst + a128(krow, c), kvsrc + c * 8);
        CP_COMMIT;
    }

    // load Q hi/lo + rel_h
    {
        const int row = tid >> 1, half = tid & 1;
        const size_t gb = ((size_t)bh << 16) | ((size_t)(q0 + row) << 6);
        const uint4* qh = (const uint4*)(g_Qhi + gb);
        const uint4* ql = (const uint4*)(g_Qlo + gb);
#pragma unroll
        for (int c = 0; c < 4; c++) {
            const int cc = half * 4 + c;
            sts128(Qh + a128(row, cc), qh[cc]);
            sts128(Ql + a128(row, cc), ql[cc]);
        }
        const float4* rs = (const float4*)(g_REL + gb);   // rel_h = first 32 floats
        float4* rd = (float4*)(RELh + row * 32);
#pragma unroll
        for (int c = 0; c < 4; c++) rd[half * 4 + c] = rs[half * 4 + c];
    }

    const int qr = wid * 16;
    const int r0 = qr + (lane >> 2);          // rows r0, r0+8

    // preload rel_w straight from gmem: rw[row][colparity][f&3]
    float rw[2][2][4];
#pragma unroll
    for (int rr = 0; rr < 2; rr++)
#pragma unroll
        for (int c = 0; c < 2; c++)
#pragma unroll
            for (int f4 = 0; f4 < 4; f4++)
                rw[rr][c][f4] = g_REL[(((size_t)bh << 16) |
                                       ((size_t)(q0 + r0 + rr * 8) << 6))
                                      + 32 + ((lane & 3) * 2 + c + f4 * 8)];

    float O[8][4];
#pragma unroll
    for (int f = 0; f < 8; f++)
#pragma unroll
        for (int v = 0; v < 4; v++) O[f][v] = 0.f;
    float m_[2] = {-1e30f, -1e30f}, l_[2] = {0.f, 0.f};

    CP_WAIT0;
    __syncthreads();

    for (int t = 0; t < 16; t++) {
        const uint32_t kvb = sb + KVB + (t & 1) * 32768;
        if (t < 15) {   // issue next K/V tile into other stage
            const uint32_t dst = sb + KVB + ((t + 1) & 1) * 32768 + arr * 8192;
            const __nv_bfloat16* src = kvsrc + ((size_t)(t + 1) << 12);  // +64 rows
#pragma unroll
            for (int c = 0; c < 8; c++) cp16(dst + a128(krow, c), src + c * 8);
            CP_COMMIT;
        }
        const uint32_t Kh = kvb, Vh = kvb + 16384;

        float S[8][4];
#pragma unroll
        for (int f = 0; f < 8; f++)
#pragma unroll
            for (int v = 0; v < 4; v++) S[f][v] = 0.f;

#pragma unroll
        for (int ks = 0; ks < 4; ks++) {
            uint32_t ah[4], al[4];
            const uint32_t aaddr = Qh + a128(qr + (lane & 7) + ((lane >> 3) & 1) * 8,
                                             2 * ks + (lane >> 4));
            ldm_x4(ah, aaddr);
            ldm_x4(al, aaddr + 16384);
#pragma unroll
            for (int g = 0; g < 4; g++) {
                uint32_t kb[4], kl[4];
                const uint32_t kaddr = Kh + a128(g * 16 + ((lane >> 4) & 1) * 8 + (lane & 7),
                                                 2 * ks + ((lane >> 3) & 1));
                ldm_x4(kb, kaddr);
                ldm_x4(kl, kaddr + 8192);
                mma16816(S[2*g],   ah, kb);     mma16816(S[2*g],   ah, kl);     mma16816(S[2*g],   al, kb);
                mma16816(S[2*g+1], ah, kb + 2); mma16816(S[2*g+1], ah, kl + 2); mma16816(S[2*g+1], al, kb + 2);
            }
        }

        // bias + online softmax
        const int khb = t * 2;
        float alpha[2];
#pragma unroll
        for (int rr = 0; rr < 2; rr++) {
            const int row = r0 + rr * 8;
            const float rh0 = RELh[row * 32 + khb], rh1 = RELh[row * 32 + khb + 1];
            float mx = m_[rr];
#pragma unroll
            for (int f = 0; f < 8; f++) {
                const float rh = (f < 4) ? rh0 : rh1;
                S[f][rr*2]   += rh + rw[rr][0][f & 3];
                S[f][rr*2+1] += rh + rw[rr][1][f & 3];
                mx = fmaxf(mx, fmaxf(S[f][rr*2], S[f][rr*2+1]));
            }
            mx = fmaxf(mx, __shfl_xor_sync(0xffffffffu, mx, 1));
            mx = fmaxf(mx, __shfl_xor_sync(0xffffffffu, mx, 2));
            alpha[rr] = fexp(m_[rr] - mx);
            m_[rr] = mx;
            float ps = 0.f;
#pragma unroll
            for (int f = 0; f < 8; f++) {
                float p0 = fexp(S[f][rr*2]   - mx);
                float p1 = fexp(S[f][rr*2+1] - mx);
                S[f][rr*2] = p0; S[f][rr*2+1] = p1;
                ps += p0 + p1;
            }
            ps += __shfl_xor_sync(0xffffffffu, ps, 1);
            ps += __shfl_xor_sync(0xffffffffu, ps, 2);
            l_[rr] = l_[rr] * alpha[rr] + ps;
#pragma unroll
            for (int f = 0; f < 8; f++) { O[f][rr*2] *= alpha[rr]; O[f][rr*2+1] *= alpha[rr]; }
        }

        // P repack (hi/lo) + PV MMAs
#pragma unroll
        for (int ks = 0; ks < 4; ks++) {
            uint32_t ph[4], pl[4];
#pragma unroll
            for (int part = 0; part < 4; part++) {
                const int f = 2 * ks + (part >> 1);
                const float x0 = S[f][(part & 1) * 2], x1 = S[f][(part & 1) * 2 + 1];
                uint32_t h = pack_bf16(x0, x1);
                ph[part] = h;
                pl[part] = pack_bf16(x0 - lo_f(h), x1 - hi_f(h));
            }
#pragma unroll
            for (int dg = 0; dg < 4; dg++) {
                uint32_t vb[4], vl[4];
                const uint32_t vaddr = Vh + a128(ks * 16 + ((lane >> 3) & 1) * 8 + (lane & 7),
                                                 2 * dg + (lane >> 4));
                ldm_x4t(vb, vaddr);
                ldm_x4t(vl, vaddr + 8192);
                mma16816(O[2*dg],   ph, vb);     mma16816(O[2*dg],   ph, vl);     mma16816(O[2*dg],   pl, vb);
                mma16816(O[2*dg+1], ph, vb + 2); mma16816(O[2*dg+1], ph, vl + 2); mma16816(O[2*dg+1], pl, vb + 2);
            }
        }
        CP_WAIT0;
        __syncthreads();
    }

    // epilogue: normalize, split hi/lo, store to g_AOhi/lo
    const float inv0 = 1.f / l_[0], inv1 = 1.f / l_[1];
    const int b = bh / NH, h = bh - b * NH;
#pragma unroll
    for (int f = 0; f < 8; f++) {
        const int col = h * HD + f * 8 + (lane & 3) * 2;
        const size_t i0 = (size_t)(b * NTOK + q0 + r0) * CDIM + col;
        const size_t i1 = (size_t)(b * NTOK + q0 + r0 + 8) * CDIM + col;
        float x0 = O[f][0] * inv0, x1 = O[f][1] * inv0;
        float x2 = O[f][2] * inv1, x3 = O[f][3] * inv1;
        uint32_t h0 = pack_bf16(x0, x1), h1 = pack_bf16(x2, x3);
        *(uint32_t*)(g_AOhi + i0) = h0;
        *(uint32_t*)(g_AOlo + i0) = pack_bf16(x0 - lo_f(h0), x1 - hi_f(h0));
        *(uint32_t*)(g_AOhi + i1) = h1;
        *(uint32_t*)(g_AOlo + i1) = pack_bf16(x2 - lo_f(h1), x3 - hi_f(h1));
    }
}

// ---------------------------------------------------------------------------
extern "C" void kernel_launch(void* const* d_in, const int* in_sizes, int n_in,
                              void* d_out, int out_size)
{
    (void)in_sizes; (void)n_in; (void)out_size;
    const float* x      = (const float*)d_in[0];
    const float* qkv_w  = (const float*)d_in[1];
    const float* qkv_b  = (const float*)d_in[2];
    const float* proj_w = (const float*)d_in[3];
    const float* proj_b = (const float*)d_in[4];
    const float* rph    = (const float*)d_in[5];
    const float* rpw    = (const float*)d_in[6];
    float* out = (float*)d_out;
    float* kv  = out + OUT_ELEMS;

    static void *pXhi, *pXlo, *pWqhi, *pWqlo, *pWphi, *pWplo, *pAOhi, *pAOlo, *pQ;
    cudaGetSymbolAddress(&pXhi, g_Xhi);   cudaGetSymbolAddress(&pXlo, g_Xlo);
    cudaGetSymbolAddress(&pWqhi, g_Wqhi); cudaGetSymbolAddress(&pWqlo, g_Wqlo);
    cudaGetSymbolAddress(&pWphi, g_Wphi); cudaGetSymbolAddress(&pWplo, g_Wplo);
    cudaGetSymbolAddress(&pAOhi, g_AOhi); cudaGetSymbolAddress(&pAOlo, g_AOlo);
    cudaGetSymbolAddress(&pQ, g_Q);

    cudaFuncSetAttribute(rel_kernel, cudaFuncAttributeMaxDynamicSharedMemorySize,
                         (64 + 63 + 63) * 68 * 4);
    cudaFuncSetAttribute(attn_mma, cudaFuncAttributeMaxDynamicSharedMemorySize, ASM_TOT);

    cvt_hilo<<<OUT_ELEMS / 1024, 256>>>(x, (__nv_bfloat16*)pXhi, (__nv_bfloat16*)pXlo, OUT_ELEMS);
    cvt_hilo<<<(3 * CDIM * CDIM) / 1024, 256>>>(qkv_w, (__nv_bfloat16*)pWqhi,
                                                (__nv_bfloat16*)pWqlo, 3 * CDIM * CDIM);
    cvt_hilo<<<(CDIM * CDIM) / 1024, 256>>>(proj_w, (__nv_bfloat16*)pWphi,
                                            (__nv_bfloat16*)pWplo, CDIM * CDIM);

    gemm_mma<<<dim3(18, 64), 256>>>(
        (const __nv_bfloat16*)pXhi, (const __nv_bfloat16*)pXlo,
        (const __nv_bfloat16*)pWqhi, (const __nv_bfloat16*)pWqlo,
        qkv_b, (float*)pQ, kv, 1);

    rel_kernel<<<dim3(16, 96), 256, (64 + 63 + 63) * 68 * 4>>>(rph, rpw);

    attn_mma<<<dim3(8, 96), 256, ASM_TOT>>>();

    gemm_mma<<<dim3(6, 64), 256>>>(
        (const __nv_bfloat16*)pAOhi, (const __nv_bfloat16*)pAOlo,
        (const __nv_bfloat16*)pWphi, (const __nv_bfloat16*)pWplo,
        proj_b, out, nullptr, 0);
}